// round 8
// baseline (speedup 1.0000x reference)
#include <cuda_runtime.h>
#include <cuda_bf16.h>
#include <cstdint>

#define TB      256
#define TILE_H  8
#define TILE_W  32
#define CIN     64
#define COUT    64
#define HH      512
#define WW      512
#define HW      (HH * WW)

// smem layout (bytes)
#define RS_A    528
#define RS_B    144
#define RS_DW   260
#define SM_A_HI 0
#define SM_A_LO (SM_A_HI + CIN * RS_A)       // 33792
#define SM_B_HI (SM_A_LO + CIN * RS_A)       // 67584
#define SM_B_LO (SM_B_HI + CIN * RS_B)       // 76800
#define SM_TOTAL (SM_B_LO + CIN * RS_B)      // 86016  (2 CTAs/SM)

__device__ __forceinline__ float axis_a(int i) {
    return (i == 0 || i == HH - 1) ? 0.70710678118654752f : 0.57735026918962576f;
}

__device__ __forceinline__ void ldsm_x4t(uint32_t* r, uint32_t addr) {
    asm volatile("ldmatrix.sync.aligned.m8n8.x4.trans.shared.b16 {%0,%1,%2,%3}, [%4];"
                 : "=r"(r[0]), "=r"(r[1]), "=r"(r[2]), "=r"(r[3]) : "r"(addr));
}
__device__ __forceinline__ void mma_bf16(float* d, const uint32_t* a, uint32_t b0, uint32_t b1) {
    asm volatile(
        "mma.sync.aligned.m16n8k16.row.col.f32.bf16.bf16.f32 "
        "{%0,%1,%2,%3}, {%4,%5,%6,%7}, {%8,%9}, {%0,%1,%2,%3};"
        : "+f"(d[0]), "+f"(d[1]), "+f"(d[2]), "+f"(d[3])
        : "r"(a[0]), "r"(a[1]), "r"(a[2]), "r"(a[3]), "r"(b0), "r"(b1));
}

// split s into bf16 hi/lo pair and store to A tiles
__device__ __forceinline__ void store_split(char* smem, int c0, int m, float s0, float s1) {
    __nv_bfloat16 h0b = __float2bfloat16(s0);
    __nv_bfloat16 h1b = __float2bfloat16(s1);
    __nv_bfloat16 l0b = __float2bfloat16(s0 - __bfloat162float(h0b));
    __nv_bfloat16 l1b = __float2bfloat16(s1 - __bfloat162float(h1b));
    uint32_t off0 = (uint32_t)(c0 * RS_A + m * 2);
    uint32_t off1 = off0 + RS_A;
    *(__nv_bfloat16*)(smem + SM_A_HI + off0) = h0b;
    *(__nv_bfloat16*)(smem + SM_A_HI + off1) = h1b;
    *(__nv_bfloat16*)(smem + SM_A_LO + off0) = l0b;
    *(__nv_bfloat16*)(smem + SM_A_LO + off1) = l1b;
}

__global__ void __launch_bounds__(TB, 2) gcn_mma_kernel(
    const float* __restrict__ x,     // [B, 64, 512, 512]
    const float* __restrict__ wmat,  // [64, 64] (c, o)
    float* __restrict__ out)         // [B, 64, 512, 512]
{
    extern __shared__ __align__(128) char smem[];
    const uint32_t sb = (uint32_t)__cvta_generic_to_shared(smem);
    float* smemf = (float*)smem;
    const int tid = threadIdx.x;
    const int wid = tid >> 5;
    const int lid = tid & 31;
    const int bx = blockIdx.x, by = blockIdx.y, b = blockIdx.z;

    // ---- B tiles: W[c][o] -> smem [c][o], bf16 hi/lo split, coalesced 32-bit STS ----
    {
        const float2* w2 = (const float2*)wmat;
        #pragma unroll
        for (int it = tid; it < CIN * COUT / 2; it += TB) {
            int c  = it >> 5;
            int o2 = it & 31;
            float2 v = w2[it];
            __nv_bfloat16 h0 = __float2bfloat16(v.x);
            __nv_bfloat16 h1 = __float2bfloat16(v.y);
            __nv_bfloat16 l0 = __float2bfloat16(v.x - __bfloat162float(h0));
            __nv_bfloat16 l1 = __float2bfloat16(v.y - __bfloat162float(h1));
            uint32_t hp = (uint32_t)__bfloat16_as_ushort(h0) |
                          ((uint32_t)__bfloat16_as_ushort(h1) << 16);
            uint32_t lp = (uint32_t)__bfloat16_as_ushort(l0) |
                          ((uint32_t)__bfloat16_as_ushort(l1) << 16);
            uint32_t off = (uint32_t)(c * RS_B + o2 * 4);
            *(uint32_t*)(smem + SM_B_HI + off) = hp;
            *(uint32_t*)(smem + SM_B_LO + off) = lp;
        }
    }

    const int h0 = by * TILE_H;
    const float* xb = x + (size_t)b * CIN * HW;
    const bool interior = (by >= 1) && (by <= 62) && (bx >= 1) && (bx <= 14);

    if (interior) {
        // ---- FAST PATH: all 3x3 weights = 1/3; aligned own-column loads + shuffles ----
        const int gw = bx * TILE_W + lid;
        const bool isHalo = (lid == 0) || (lid == 31);
        const int hcol = (lid == 0) ? (gw - 1) : (gw + 1);   // lane0: left halo, lane31: right halo

        #pragma unroll 1
        for (int pass = 0; pass < 4; pass++) {
            const int c0 = (wid + 8 * pass) * 2;
            float hs[2][TILE_H + 2];
            #pragma unroll
            for (int cc = 0; cc < 2; cc++) {
                const float* p = xb + (size_t)(c0 + cc) * HW + (size_t)(h0 - 1) * WW;
                float u[TILE_H + 2], uh[TILE_H + 2];
                #pragma unroll
                for (int r = 0; r < TILE_H + 2; r++) u[r] = p[r * WW + gw];
                #pragma unroll
                for (int r = 0; r < TILE_H + 2; r++)
                    uh[r] = isHalo ? p[r * WW + hcol] : 0.0f;
                #pragma unroll
                for (int r = 0; r < TILE_H + 2; r++) {
                    float l  = __shfl_up_sync(0xFFFFFFFFu, u[r], 1);
                    float rr = __shfl_down_sync(0xFFFFFFFFu, u[r], 1);
                    if (lid == 0)  l  = uh[r];
                    if (lid == 31) rr = uh[r];
                    hs[cc][r] = l + u[r] + rr;
                }
            }
            #pragma unroll
            for (int r = 0; r < TILE_H; r++) {
                float s0 = (hs[0][r] + hs[0][r + 1] + hs[0][r + 2]) * 0.33333334f;
                float s1 = (hs[1][r] + hs[1][r + 1] + hs[1][r + 2]) * 0.33333334f;
                store_split(smem, c0, r * 32 + lid, s0, s1);
            }
        }
    } else {
        // ---- BORDER PATH (R7-verified): weighted, predicated ----
        const int gwl = bx * TILE_W - 1 + lid;
        const float aw0 = ((unsigned)gwl < WW) ? axis_a(gwl) : 0.0f;
        const float aw1 = axis_a(gwl + 1);
        const float aw2 = ((unsigned)(gwl + 2) < WW) ? axis_a(gwl + 2) : 0.0f;
        const bool ok0 = ((unsigned)gwl < WW);
        const bool ok2 = ((unsigned)(gwl + 2) < WW);

        #pragma unroll 1
        for (int pass = 0; pass < 4; pass++) {
            const int c0 = (wid + 8 * pass) * 2;
            float hs[2][TILE_H + 2];
            #pragma unroll
            for (int cc = 0; cc < 2; cc++) {
                float v[TILE_H + 2][3];
                const float* p = xb + (size_t)(c0 + cc) * HW + (size_t)(h0 - 1) * WW + gwl;
                #pragma unroll
                for (int r = 0; r < TILE_H + 2; r++) {
                    const bool rowok = ((unsigned)(h0 - 1 + r) < HH);
                    v[r][0] = (rowok && ok0) ? p[0] : 0.0f;
                    v[r][1] = rowok ? p[1] : 0.0f;
                    v[r][2] = (rowok && ok2) ? p[2] : 0.0f;
                    p += WW;
                }
                #pragma unroll
                for (int r = 0; r < TILE_H + 2; r++) {
                    float hsum = v[r][1] * aw1;
                    hsum = fmaf(v[r][0], aw0, hsum);
                    hsum = fmaf(v[r][2], aw2, hsum);
                    hs[cc][r] = hsum * axis_a(h0 - 1 + r);
                }
            }
            #pragma unroll
            for (int r = 0; r < TILE_H; r++) {
                float s0 = hs[0][r] + hs[0][r + 1] + hs[0][r + 2];
                float s1 = hs[1][r] + hs[1][r + 1] + hs[1][r + 2];
                store_split(smem, c0, r * 32 + lid, s0, s1);
            }
        }
    }
    __syncthreads();

    // ---- MMA: D[256,64] = A * B, 3 bf16 splits, fragments loaded once per k-tile ----
    const uint32_t a_off = (uint32_t)((lid & 7) + ((lid >> 4) & 1) * 8) * RS_A
                         + (uint32_t)(wid * 32 + ((lid >> 3) & 1) * 8) * 2;
    const uint32_t b_off = (uint32_t)((lid & 7) + ((lid >> 3) & 1) * 8) * RS_B
                         + (uint32_t)(((lid >> 4) & 1) * 8) * 2;

    float acc[2][8][4];
    #pragma unroll
    for (int mt = 0; mt < 2; mt++)
        #pragma unroll
        for (int nt = 0; nt < 8; nt++)
            #pragma unroll
            for (int k = 0; k < 4; k++) acc[mt][nt][k] = 0.0f;

    #pragma unroll
    for (int kt = 0; kt < 4; kt++) {
        uint32_t bh[4][4], bl[4][4];
        #pragma unroll
        for (int p = 0; p < 4; p++) {
            ldsm_x4t(bh[p], sb + SM_B_HI + b_off + (uint32_t)(kt * 16 * RS_B + p * 32));
            ldsm_x4t(bl[p], sb + SM_B_LO + b_off + (uint32_t)(kt * 16 * RS_B + p * 32));
        }
        uint32_t ah[2][4], al[2][4];
        #pragma unroll
        for (int mt = 0; mt < 2; mt++) {
            ldsm_x4t(ah[mt], sb + SM_A_HI + a_off + (uint32_t)(kt * 16 * RS_A + mt * 32));
            ldsm_x4t(al[mt], sb + SM_A_LO + a_off + (uint32_t)(kt * 16 * RS_A + mt * 32));
        }
        #pragma unroll
        for (int mt = 0; mt < 2; mt++)
            #pragma unroll
            for (int nt = 0; nt < 8; nt++)
                mma_bf16(acc[mt][nt], ah[mt], bh[nt >> 1][(nt & 1) * 2], bh[nt >> 1][(nt & 1) * 2 + 1]);
        #pragma unroll
        for (int mt = 0; mt < 2; mt++)
            #pragma unroll
            for (int nt = 0; nt < 8; nt++)
                mma_bf16(acc[mt][nt], ah[mt], bl[nt >> 1][(nt & 1) * 2], bl[nt >> 1][(nt & 1) * 2 + 1]);
        #pragma unroll
        for (int mt = 0; mt < 2; mt++)
            #pragma unroll
            for (int nt = 0; nt < 8; nt++)
                mma_bf16(acc[mt][nt], al[mt], bh[nt >> 1][(nt & 1) * 2], bh[nt >> 1][(nt & 1) * 2 + 1]);
    }

    // ---- epilogue: dp-scale into smem D stage (overlays A), then coalesced STG.128 ----
    __syncthreads();

    const int gh = h0 + wid;
    const float ah_ = axis_a(gh);
    #pragma unroll
    for (int mt = 0; mt < 2; mt++) {
        #pragma unroll
        for (int half = 0; half < 2; half++) {
            int tx = mt * 16 + half * 8 + (lid >> 2);
            float dp = ah_ * axis_a(bx * TILE_W + tx);
            int m = wid * 32 + tx;
            #pragma unroll
            for (int nt = 0; nt < 8; nt++) {
                int ch = nt * 8 + (lid & 3) * 2;
                smemf[(uint32_t)(ch * RS_DW + m)]       = acc[mt][nt][half * 2 + 0] * dp;
                smemf[(uint32_t)((ch + 1) * RS_DW + m)] = acc[mt][nt][half * 2 + 1] * dp;
            }
        }
    }
    __syncthreads();

    float* ob = out + (size_t)b * COUT * HW + (size_t)h0 * WW + bx * TILE_W;
    #pragma unroll
    for (int i = 0; i < 16; i++) {
        int idx = tid + i * TB;
        int k = idx & 7;
        int r = (idx >> 3) & 7;
        int ch = idx >> 6;
        float4 val = *(float4*)(smemf + (uint32_t)(ch * RS_DW + r * 32 + k * 4));
        *(float4*)(ob + (size_t)ch * HW + (size_t)r * WW + k * 4) = val;
    }
}

extern "C" void kernel_launch(void* const* d_in, const int* in_sizes, int n_in,
                              void* d_out, int out_size)
{
    const float* x = (const float*)d_in[0];   // [4, 64, 512, 512]
    const float* w = (const float*)d_in[1];   // [1, 64, 64]
    float* out = (float*)d_out;

    cudaFuncSetAttribute(gcn_mma_kernel,
                         cudaFuncAttributeMaxDynamicSharedMemorySize, SM_TOTAL);

    dim3 grid(WW / TILE_W, HH / TILE_H, 4);
    gcn_mma_kernel<<<grid, TB, SM_TOTAL>>>(x, w, out);
}

// round 9
// speedup vs baseline: 1.0470x; 1.0470x over previous
#include <cuda_runtime.h>
#include <cuda_bf16.h>
#include <cstdint>

#define TB      256
#define TILE_H  4
#define TILE_W  64
#define CIN     64
#define COUT    64
#define HH      512
#define WW      512
#define HW      (HH * WW)

// smem layout (bytes)
// A stored [c][m], m=256 (m = r*64+col): row = 512B + 16 pad = 528B
// B stored [c][o]: row = 128B + 16 pad = 144B
// D staging overlays A: [ch][m=256] fp32, row stride 260 words
#define RS_A    528
#define RS_B    144
#define RS_DW   260
#define SM_A_HI 0
#define SM_A_LO (SM_A_HI + CIN * RS_A)       // 33792
#define SM_B_HI (SM_A_LO + CIN * RS_A)       // 67584
#define SM_B_LO (SM_B_HI + CIN * RS_B)       // 76800
#define SM_TOTAL (SM_B_LO + CIN * RS_B)      // 86016  (2 CTAs/SM)

__device__ __forceinline__ float axis_a(int i) {
    return (i == 0 || i == HH - 1) ? 0.70710678118654752f : 0.57735026918962576f;
}

__device__ __forceinline__ void ldsm_x4t(uint32_t* r, uint32_t addr) {
    asm volatile("ldmatrix.sync.aligned.m8n8.x4.trans.shared.b16 {%0,%1,%2,%3}, [%4];"
                 : "=r"(r[0]), "=r"(r[1]), "=r"(r[2]), "=r"(r[3]) : "r"(addr));
}
__device__ __forceinline__ void mma_bf16(float* d, const uint32_t* a, uint32_t b0, uint32_t b1) {
    asm volatile(
        "mma.sync.aligned.m16n8k16.row.col.f32.bf16.bf16.f32 "
        "{%0,%1,%2,%3}, {%4,%5,%6,%7}, {%8,%9}, {%0,%1,%2,%3};"
        : "+f"(d[0]), "+f"(d[1]), "+f"(d[2]), "+f"(d[3])
        : "r"(a[0]), "r"(a[1]), "r"(a[2]), "r"(a[3]), "r"(b0), "r"(b1));
}

__global__ void __launch_bounds__(TB, 2) gcn_mma_kernel(
    const float* __restrict__ x,     // [B, 64, 512, 512]
    const float* __restrict__ wmat,  // [64, 64] (c, o)
    float* __restrict__ out)         // [B, 64, 512, 512]
{
    extern __shared__ __align__(128) char smem[];
    const uint32_t sb = (uint32_t)__cvta_generic_to_shared(smem);
    float* smemf = (float*)smem;
    const int tid = threadIdx.x;
    const int wid = tid >> 5;
    const int lid = tid & 31;
    const int bx = blockIdx.x, by = blockIdx.y, b = blockIdx.z;

    // ---- B tiles: W[c][o] -> smem [c][o], bf16 hi/lo split, coalesced 32-bit STS ----
    {
        const float2* w2 = (const float2*)wmat;
        #pragma unroll
        for (int it = tid; it < CIN * COUT / 2; it += TB) {
            int c  = it >> 5;
            int o2 = it & 31;
            float2 v = w2[it];
            __nv_bfloat16 h0 = __float2bfloat16(v.x);
            __nv_bfloat16 h1 = __float2bfloat16(v.y);
            __nv_bfloat16 l0 = __float2bfloat16(v.x - __bfloat162float(h0));
            __nv_bfloat16 l1 = __float2bfloat16(v.y - __bfloat162float(h1));
            uint32_t hp = (uint32_t)__bfloat16_as_ushort(h0) |
                          ((uint32_t)__bfloat16_as_ushort(h1) << 16);
            uint32_t lp = (uint32_t)__bfloat16_as_ushort(l0) |
                          ((uint32_t)__bfloat16_as_ushort(l1) << 16);
            uint32_t off = (uint32_t)(c * RS_B + o2 * 4);
            *(uint32_t*)(smem + SM_B_HI + off) = hp;
            *(uint32_t*)(smem + SM_B_LO + off) = lp;
        }
    }

    // ---- stencil: lane owns 2 columns (float2 loads), shuffles for seams ----
    const int h0 = by * TILE_H;
    const int cbase = bx * TILE_W + 2 * lid;       // lane's first column (even, 8B-aligned)
    const float* xb = x + (size_t)b * CIN * HW;

    // per-lane horizontal weights for window cols c-1, c, c+1, c+2
    const bool lok = (cbase - 1 >= 0);             // false only for bx==0, lid==0
    const bool rok = (cbase + 2 <= WW - 1);        // false only for bx==7, lid==31
    const float w0 = lok ? axis_a(cbase - 1) : 0.0f;
    const float w1 = axis_a(cbase);
    const float w2 = axis_a(cbase + 1);
    const float w3 = rok ? axis_a(cbase + 2) : 0.0f;
    // halo column: lane 0 -> left (cbase-1), lane 31 -> right (cbase+2)
    const int haloc = (lid == 0) ? (cbase - 1) : (cbase + 2);
    const bool hvalid = (lid == 0) ? lok : ((lid == 31) ? rok : false);

    #pragma unroll 1
    for (int pass = 0; pass < 4; pass++) {
        const int c0 = (wid + 8 * pass) * 2;

        // batch all loads first (high MLP)
        float2 u[2][TILE_H + 2];
        float  uh[2][TILE_H + 2];
        #pragma unroll
        for (int cc = 0; cc < 2; cc++) {
            const float* p = xb + (size_t)(c0 + cc) * HW + (size_t)(h0 - 1) * WW;
            #pragma unroll
            for (int r = 0; r < TILE_H + 2; r++) {
                const bool rowok = ((unsigned)(h0 - 1 + r) < HH);
                u[cc][r]  = rowok ? *(const float2*)(p + (size_t)r * WW + cbase)
                                  : make_float2(0.0f, 0.0f);
                uh[cc][r] = (rowok && hvalid) ? p[(size_t)r * WW + haloc] : 0.0f;
            }
        }

        // horizontal weighted 3-sums + vertical weight fold
        float2 hs[2][TILE_H + 2];
        #pragma unroll
        for (int r = 0; r < TILE_H + 2; r++) {
            const float av = axis_a(h0 - 1 + r);
            #pragma unroll
            for (int cc = 0; cc < 2; cc++) {
                float lx = __shfl_up_sync(0xFFFFFFFFu, u[cc][r].y, 1);
                float ry = __shfl_down_sync(0xFFFFFFFFu, u[cc][r].x, 1);
                if (lid == 0)  lx = uh[cc][r];
                if (lid == 31) ry = uh[cc][r];
                float t  = fmaf(w2, u[cc][r].y, w1 * u[cc][r].x);
                float hx = fmaf(w0, lx, t);
                float hy = fmaf(w3, ry, t);
                hs[cc][r] = make_float2(hx * av, hy * av);
            }
        }

        // vertical 3-sum, bf16 split, packed STS (pair m, m+1 per channel)
        #pragma unroll
        for (int r = 0; r < TILE_H; r++) {
            const int m = r * 64 + 2 * lid;
            #pragma unroll
            for (int cc = 0; cc < 2; cc++) {
                float sx = hs[cc][r].x + hs[cc][r + 1].x + hs[cc][r + 2].x;
                float sy = hs[cc][r].y + hs[cc][r + 1].y + hs[cc][r + 2].y;
                __nv_bfloat16 hxb = __float2bfloat16(sx);
                __nv_bfloat16 hyb = __float2bfloat16(sy);
                __nv_bfloat16 lxb = __float2bfloat16(sx - __bfloat162float(hxb));
                __nv_bfloat16 lyb = __float2bfloat16(sy - __bfloat162float(hyb));
                uint32_t hp = (uint32_t)__bfloat16_as_ushort(hxb) |
                              ((uint32_t)__bfloat16_as_ushort(hyb) << 16);
                uint32_t lp = (uint32_t)__bfloat16_as_ushort(lxb) |
                              ((uint32_t)__bfloat16_as_ushort(lyb) << 16);
                uint32_t off = (uint32_t)((c0 + cc) * RS_A + m * 2);
                *(uint32_t*)(smem + SM_A_HI + off) = hp;
                *(uint32_t*)(smem + SM_A_LO + off) = lp;
            }
        }
    }
    __syncthreads();

    // ---- MMA: D[256,64] = A * B, 3 bf16 splits, fragments loaded once per k-tile ----
    const uint32_t a_off = (uint32_t)((lid & 7) + ((lid >> 4) & 1) * 8) * RS_A
                         + (uint32_t)(wid * 32 + ((lid >> 3) & 1) * 8) * 2;
    const uint32_t b_off = (uint32_t)((lid & 7) + ((lid >> 3) & 1) * 8) * RS_B
                         + (uint32_t)(((lid >> 4) & 1) * 8) * 2;

    float acc[2][8][4];
    #pragma unroll
    for (int mt = 0; mt < 2; mt++)
        #pragma unroll
        for (int nt = 0; nt < 8; nt++)
            #pragma unroll
            for (int k = 0; k < 4; k++) acc[mt][nt][k] = 0.0f;

    #pragma unroll
    for (int kt = 0; kt < 4; kt++) {
        uint32_t bh[4][4], bl[4][4];
        #pragma unroll
        for (int p = 0; p < 4; p++) {
            ldsm_x4t(bh[p], sb + SM_B_HI + b_off + (uint32_t)(kt * 16 * RS_B + p * 32));
            ldsm_x4t(bl[p], sb + SM_B_LO + b_off + (uint32_t)(kt * 16 * RS_B + p * 32));
        }
        uint32_t ah[2][4], al[2][4];
        #pragma unroll
        for (int mt = 0; mt < 2; mt++) {
            ldsm_x4t(ah[mt], sb + SM_A_HI + a_off + (uint32_t)(kt * 16 * RS_A + mt * 32));
            ldsm_x4t(al[mt], sb + SM_A_LO + a_off + (uint32_t)(kt * 16 * RS_A + mt * 32));
        }
        #pragma unroll
        for (int mt = 0; mt < 2; mt++)
            #pragma unroll
            for (int nt = 0; nt < 8; nt++)
                mma_bf16(acc[mt][nt], ah[mt], bh[nt >> 1][(nt & 1) * 2], bh[nt >> 1][(nt & 1) * 2 + 1]);
        #pragma unroll
        for (int mt = 0; mt < 2; mt++)
            #pragma unroll
            for (int nt = 0; nt < 8; nt++)
                mma_bf16(acc[mt][nt], ah[mt], bl[nt >> 1][(nt & 1) * 2], bl[nt >> 1][(nt & 1) * 2 + 1]);
        #pragma unroll
        for (int mt = 0; mt < 2; mt++)
            #pragma unroll
            for (int nt = 0; nt < 8; nt++)
                mma_bf16(acc[mt][nt], al[mt], bh[nt >> 1][(nt & 1) * 2], bh[nt >> 1][(nt & 1) * 2 + 1]);
    }

    // ---- epilogue: dp-scale into smem D stage (overlays A), then coalesced STG ----
    __syncthreads();

    // warp w owns m in [32w, 32w+32): image row r = w>>1, cols (w&1)*32 + [0,32)
    const int gh = h0 + (wid >> 1);
    const int colb = (wid & 1) * 32;
    const float ah_ = axis_a(gh);
    #pragma unroll
    for (int mt = 0; mt < 2; mt++) {
        #pragma unroll
        for (int half = 0; half < 2; half++) {
            int tx = mt * 16 + half * 8 + (lid >> 2);
            float dp = ah_ * axis_a(bx * TILE_W + colb + tx);
            int m = wid * 32 + tx;
            #pragma unroll
            for (int nt = 0; nt < 8; nt++) {
                int ch = nt * 8 + (lid & 3) * 2;
                smemf[(uint32_t)(ch * RS_DW + m)]       = acc[mt][nt][half * 2 + 0] * dp;
                smemf[(uint32_t)((ch + 1) * RS_DW + m)] = acc[mt][nt][half * 2 + 1] * dp;
            }
        }
    }
    __syncthreads();

    // readback: 4096 float4 units; [ch][r (4)][64 cols]
    float* ob = out + (size_t)b * COUT * HW + (size_t)h0 * WW + bx * TILE_W;
    #pragma unroll
    for (int i = 0; i < 16; i++) {
        int idx = tid + i * TB;
        int k  = idx & 15;
        int rr = (idx >> 4) & 3;
        int ch = idx >> 6;
        float4 val = *(float4*)(smemf + (uint32_t)(ch * RS_DW + rr * 64 + k * 4));
        *(float4*)(ob + (size_t)ch * HW + (size_t)rr * WW + k * 4) = val;
    }
}

extern "C" void kernel_launch(void* const* d_in, const int* in_sizes, int n_in,
                              void* d_out, int out_size)
{
    const float* x = (const float*)d_in[0];   // [4, 64, 512, 512]
    const float* w = (const float*)d_in[1];   // [1, 64, 64]
    float* out = (float*)d_out;

    cudaFuncSetAttribute(gcn_mma_kernel,
                         cudaFuncAttributeMaxDynamicSharedMemorySize, SM_TOTAL);

    dim3 grid(WW / TILE_W, HH / TILE_H, 4);
    gcn_mma_kernel<<<grid, TB, SM_TOTAL>>>(x, w, out);
}